// round 6
// baseline (speedup 1.0000x reference)
#include <cuda_runtime.h>
#include <math.h>

// Problem constants
#define BB 64
#define TT 256
#define DD 512
#define HH 1024         // H1 == H2
#define G4 4096         // 4*H
#define OO 512
#define MTOT (BB*TT)    // 16384

// ---------------------------------------------------------------------------
// Static device scratch (no allocations allowed in kernel_launch)
// ---------------------------------------------------------------------------
__device__ float g_xz[(size_t)MTOT * G4];     // 256 MB: xz for current layer (reused)
__device__ float g_seq1[(size_t)MTOT * HH];   // 64 MB: layer-1 hidden sequence [t][b][u]
__device__ float g_hbuf[2][BB * HH];          // ping-pong h
__device__ float g_Wp[(size_t)HH * G4];       // permuted W (gate-interleaved)
__device__ float g_Up[(size_t)HH * G4];       // permuted U (gate-interleaved)
__device__ float g_bp[G4];                    // permuted bias
__device__ unsigned g_bar;                    // grid barrier counter

// ---------------------------------------------------------------------------
// Permute weights into gate-interleaved layout: dst[k][u*4+g] = src[k][g*H+u]
// dst_sel: 0 = g_Wp, 1 = g_Up, 2 = g_bp
// ---------------------------------------------------------------------------
__global__ void permute_gates(const float* __restrict__ src, int K, int dst_sel)
{
    float* dst = (dst_sel == 0) ? g_Wp : (dst_sel == 1) ? g_Up : g_bp;
    int idx = blockIdx.x * blockDim.x + threadIdx.x;
    int total = K * G4;
    if (idx >= total) return;
    int k   = idx >> 12;       // / 4096
    int col = idx & 4095;
    int u   = col >> 2;
    int g   = col & 3;
    dst[idx] = src[(size_t)k * G4 + g * HH + u];
}

// ---------------------------------------------------------------------------
// Zero h0 and the grid-barrier counter before each layer
// ---------------------------------------------------------------------------
__global__ void zero_hc()
{
    int idx = blockIdx.x * blockDim.x + threadIdx.x;
    if (idx < BB * HH) g_hbuf[0][idx] = 0.f;
    if (idx == 0) g_bar = 0u;
}

// ---------------------------------------------------------------------------
// Big GEMM: out[m][n] = sum_k A[m][k] * Wp[k][n] + bp[n]
//   m = t*B + b (output is [T][B][4096] gate-interleaved)
//   MODE 0: A = x with layout [b][t][d] (K = 512), A passed as param
//   MODE 1: A = g_seq1, plain row-major [m][k] (K = 1024)
// 128x128x16 tiles, 256 threads, 8x8 microtile (split 4+4)
// ---------------------------------------------------------------------------
template<int MODE>
__global__ __launch_bounds__(256) void gemm_big(const float* __restrict__ Ain, int K)
{
    __shared__ float As[16][136];
    __shared__ float Bs[16][136];

    const int tid  = threadIdx.x;
    const int tx   = tid & 15;
    const int ty   = tid >> 4;
    const int row0 = blockIdx.y * 128;
    const int n0   = blockIdx.x * 128;

    const float* A = (MODE == 0) ? Ain : (const float*)g_seq1;

    float bias[8];
#pragma unroll
    for (int j = 0; j < 4; j++) {
        bias[j]     = g_bp[n0 + tx * 4 + j];
        bias[4 + j] = g_bp[n0 + 64 + tx * 4 + j];
    }
    float acc[8][8];
#pragma unroll
    for (int r = 0; r < 8; r++)
#pragma unroll
        for (int c = 0; c < 8; c++) acc[r][c] = bias[c];

    for (int k0 = 0; k0 < K; k0 += 16) {
        // A tile (128 x 16), stored transposed As[k][m]
#pragma unroll
        for (int l = 0; l < 2; l++) {
            int lin = tid + l * 256;
            int m = lin >> 2, q = lin & 3;
            int mg = row0 + m;
            const float* ap;
            if (MODE == 0) {
                int t_ = mg >> 6, b_ = mg & 63;
                ap = A + ((size_t)(b_ * TT + t_)) * DD;
            } else {
                ap = A + (size_t)mg * K;
            }
            float4 v = *(const float4*)(ap + k0 + q * 4);
            As[q * 4 + 0][m] = v.x;
            As[q * 4 + 1][m] = v.y;
            As[q * 4 + 2][m] = v.z;
            As[q * 4 + 3][m] = v.w;
        }
        // B tile (16 x 128)
#pragma unroll
        for (int l = 0; l < 2; l++) {
            int lin = tid + l * 256;
            int kk = lin >> 5, q = lin & 31;
            float4 v = *(const float4*)(g_Wp + (size_t)(k0 + kk) * G4 + n0 + q * 4);
            *(float4*)&Bs[kk][q * 4] = v;
        }
        __syncthreads();
#pragma unroll
        for (int k = 0; k < 16; k++) {
            float a[8], b[8];
            *(float4*)&a[0] = *(float4*)&As[k][ty * 4];
            *(float4*)&a[4] = *(float4*)&As[k][64 + ty * 4];
            *(float4*)&b[0] = *(float4*)&Bs[k][tx * 4];
            *(float4*)&b[4] = *(float4*)&Bs[k][64 + tx * 4];
#pragma unroll
            for (int r = 0; r < 8; r++)
#pragma unroll
                for (int c = 0; c < 8; c++)
                    acc[r][c] += a[r] * b[c];
        }
        __syncthreads();
    }

#pragma unroll
    for (int r = 0; r < 8; r++) {
        int m = row0 + ((r < 4) ? (ty * 4 + r) : (64 + ty * 4 + (r - 4)));
        float* op = g_xz + (size_t)m * G4 + n0;
        float4 v0 = make_float4(acc[r][0], acc[r][1], acc[r][2], acc[r][3]);
        float4 v1 = make_float4(acc[r][4], acc[r][5], acc[r][6], acc[r][7]);
        *(float4*)(op + tx * 4)      = v0;
        *(float4*)(op + 64 + tx * 4) = v1;
    }
}

// ---------------------------------------------------------------------------
// Persistent recurrence kernel: one launch runs all TT steps of a layer.
// Grid: 128 CTAs (each owns 8 units = 32 gate-interleaved columns), 256 thr,
// 1 CTA per SM (152 KB dynamic smem) so all CTAs are co-resident; steps are
// separated by an atomic-counter grid barrier.
//
// Per CTA:
//   - U slice [1024 x 32] loaded into smem ONCE per layer
//   - c state lives in registers (2 values/thread, CTA-private cells)
//   - h chunks (64 x 32) double-buffered in smem w/ register prefetch (__ldcg:
//     h is written by other SMs between steps, L1 would be stale)
// ---------------------------------------------------------------------------
#define SMEM_U   0                 // 1024*32 floats = 32768
#define SMEM_H   32768             // 2 * 64*32   = 4096
#define SMEM_Z   (32768 + 4096)    // 64*33       = 2112
#define SMEM_FLOATS (32768 + 4096 + 2112)

__global__ __launch_bounds__(256) void lstm_layer_persist(int layer)
{
    extern __shared__ float sm[];
    float* sU  = sm + SMEM_U;
    float* sH  = sm + SMEM_H;
    float* sZ  = sm + SMEM_Z;

    const int tid = threadIdx.x;
    const int tx  = tid & 31;
    const int wy  = tid >> 5;            // 0..7
    const int c0  = blockIdx.x * 32;     // column base in [0, 4096)

    // ---- load U slice into smem (once) ----
    for (int i = tid; i < 8192; i += 256) {
        int k = i >> 3, q = i & 7;
        float4 v = *(const float4*)(g_Up + (size_t)k * G4 + c0 + q * 4);
        *(float4*)&sU[k * 32 + q * 4] = v;
    }

    // ---- c state in registers (CTA-private cells) ----
    float creg0 = 0.f, creg1 = 0.f;

    // precomputed indices for h-chunk staging (2 float4 per thread)
    const int hm0 = tid >> 3,          hq0 = (tid & 7) * 4;
    const int hm1 = (tid + 256) >> 3,  hq1 = (tid & 7) * 4;

    __syncthreads();

    unsigned bar_target = 0;
    volatile unsigned* barp = &g_bar;

    for (int t = 0; t < TT; t++) {
        const float* xz_t   = g_xz + (size_t)t * BB * G4;
        const float* h_prev = g_hbuf[t & 1];
        float*       h_new  = g_hbuf[(t + 1) & 1];

        // acc init = xz (bias already folded in)
        float acc[8];
#pragma unroll
        for (int r = 0; r < 8; r++)
            acc[r] = xz_t[(size_t)(wy * 8 + r) * G4 + c0 + tx];

        // preload h chunk 0 (L2 reads — bypass stale L1)
        float4 pre0 = __ldcg((const float4*)(h_prev + (size_t)hm0 * HH + hq0));
        float4 pre1 = __ldcg((const float4*)(h_prev + (size_t)hm1 * HH + hq1));
        *(float4*)&sH[hm0 * 32 + hq0] = pre0;
        *(float4*)&sH[hm1 * 32 + hq1] = pre1;
        __syncthreads();

        int buf = 0;
        for (int k0 = 0; k0 < HH; k0 += 32) {
            const bool more = (k0 + 32) < HH;
            if (more) {
                pre0 = __ldcg((const float4*)(h_prev + (size_t)hm0 * HH + k0 + 32 + hq0));
                pre1 = __ldcg((const float4*)(h_prev + (size_t)hm1 * HH + k0 + 32 + hq1));
            }
            const float* hb = &sH[buf * 2048];
            const float* ub = &sU[k0 * 32];
#pragma unroll
            for (int q = 0; q < 8; q++) {
                float u0 = ub[(q * 4 + 0) * 32 + tx];
                float u1 = ub[(q * 4 + 1) * 32 + tx];
                float u2 = ub[(q * 4 + 2) * 32 + tx];
                float u3 = ub[(q * 4 + 3) * 32 + tx];
#pragma unroll
                for (int r = 0; r < 8; r++) {
                    float4 hv = *(const float4*)&hb[(wy * 8 + r) * 32 + q * 4];
                    acc[r] = fmaf(hv.w, u3, fmaf(hv.z, u2,
                             fmaf(hv.y, u1, fmaf(hv.x, u0, acc[r]))));
                }
            }
            if (more) {
                float* nb = &sH[(buf ^ 1) * 2048];
                *(float4*)&nb[hm0 * 32 + hq0] = pre0;
                *(float4*)&nb[hm1 * 32 + hq1] = pre1;
            }
            buf ^= 1;
            __syncthreads();
        }

        // stage z tile, then gates
#pragma unroll
        for (int r = 0; r < 8; r++) sZ[(wy * 8 + r) * 33 + tx] = acc[r];
        __syncthreads();

#pragma unroll
        for (int l = 0; l < 2; l++) {
            int item = tid + l * 256;   // 512 (m, unit) items, fixed per thread
            int m = item >> 3, u = item & 7;
            float zi = sZ[m * 33 + u * 4 + 0];
            float zf = sZ[m * 33 + u * 4 + 1];
            float zg = sZ[m * 33 + u * 4 + 2];
            float zo = sZ[m * 33 + u * 4 + 3];
            float cold = (l == 0) ? creg0 : creg1;
            float si = 1.f / (1.f + __expf(-zi));
            float sf = 1.f / (1.f + __expf(-zf));
            float so = 1.f / (1.f + __expf(-zo));
            float tg = tanhf(zg);
            float cn = sf * cold + si * tg;
            float hn = so * tanhf(cn);
            if (l == 0) creg0 = cn; else creg1 = cn;
            int uu  = (c0 >> 2) + u;
            int idx = m * HH + uu;
            h_new[idx] = hn;
            if (layer == 0)
                g_seq1[(size_t)t * BB * HH + idx] = hn;
        }

        // grid barrier (not needed after the final step)
        if (t < TT - 1) {
            __threadfence();
            __syncthreads();            // all CTA writes done + fenced
            bar_target += 128;
            if (tid == 0) {
                atomicAdd(&g_bar, 1u);
                while (*barp < bar_target) { }
            }
            __syncthreads();
        }
    }
}

// ---------------------------------------------------------------------------
// Final dense: out[b][o] = h_last[b] . Wd[:,o] + bd[o]
// ---------------------------------------------------------------------------
__global__ void dense_out(const float* __restrict__ Wd, const float* __restrict__ bd,
                          float* __restrict__ out)
{
    int b = blockIdx.x;        // 64
    int o = threadIdx.x;       // 512
    const float* hp = g_hbuf[0] + (size_t)b * HH;   // T even -> final h in buf 0
    float acc = bd[o];
#pragma unroll 8
    for (int k = 0; k < HH; k++)
        acc += hp[k] * Wd[(size_t)k * OO + o];
    out[(size_t)b * OO + o] = acc;
}

// ---------------------------------------------------------------------------
// Launch sequence (graph-capturable: kernel launches only)
// ---------------------------------------------------------------------------
extern "C" void kernel_launch(void* const* d_in, const int* in_sizes, int n_in,
                              void* d_out, int out_size)
{
    const float* x  = (const float*)d_in[0];
    const float* W1 = (const float*)d_in[1];
    const float* U1 = (const float*)d_in[2];
    const float* b1 = (const float*)d_in[3];
    const float* W2 = (const float*)d_in[4];
    const float* U2 = (const float*)d_in[5];
    const float* b2 = (const float*)d_in[6];
    const float* Wd = (const float*)d_in[7];
    const float* bd = (const float*)d_in[8];
    float* out = (float*)d_out;

    const int smem_bytes = SMEM_FLOATS * sizeof(float);   // 155,904 B
    cudaFuncSetAttribute(lstm_layer_persist,
                         cudaFuncAttributeMaxDynamicSharedMemorySize, smem_bytes);

    dim3 gemm_grid(G4 / 128, MTOT / 128);

    // ---- Layer 1 ----
    permute_gates<<<(DD * G4 + 255) / 256, 256>>>(W1, DD, 0);
    permute_gates<<<(HH * G4 + 255) / 256, 256>>>(U1, HH, 1);
    permute_gates<<<(G4 + 255) / 256, 256>>>(b1, 1, 2);
    zero_hc<<<(BB * HH + 255) / 256, 256>>>();
    gemm_big<0><<<gemm_grid, 256>>>(x, DD);
    lstm_layer_persist<<<128, 256, smem_bytes>>>(0);

    // ---- Layer 2 ----
    permute_gates<<<(HH * G4 + 255) / 256, 256>>>(W2, HH, 0);
    permute_gates<<<(HH * G4 + 255) / 256, 256>>>(U2, HH, 1);
    permute_gates<<<(G4 + 255) / 256, 256>>>(b2, 1, 2);
    zero_hc<<<(BB * HH + 255) / 256, 256>>>();
    gemm_big<1><<<gemm_grid, 256>>>(nullptr, HH);
    lstm_layer_persist<<<128, 256, smem_bytes>>>(1);

    // ---- Dense head ----
    dense_out<<<BB, OO>>>(Wd, bd, out);
}

// round 7
// speedup vs baseline: 1.1677x; 1.1677x over previous
#include <cuda_runtime.h>
#include <math.h>

// Problem constants
#define BB 64
#define TT 256
#define DD 512
#define HH 1024         // H1 == H2
#define G4 4096         // 4*H
#define OO 512
#define MTOT (BB*TT)    // 16384

typedef unsigned long long ull;

// ---------------------------------------------------------------------------
// f32x2 packed-FMA helpers (sm_103a FFMA2)
// ---------------------------------------------------------------------------
__device__ __forceinline__ void ffma2(ull& d, ull a, ull b) {
    asm("fma.rn.f32x2 %0, %1, %2, %0;" : "+l"(d) : "l"(a), "l"(b));
}
__device__ __forceinline__ ull pack_dup(float x) {
    ull r; asm("mov.b64 %0, {%1, %1};" : "=l"(r) : "f"(x)); return r;
}
__device__ __forceinline__ ull pack2(float lo, float hi) {
    ull r; asm("mov.b64 %0, {%1, %2};" : "=l"(r) : "f"(lo), "f"(hi)); return r;
}
__device__ __forceinline__ float lo_f(ull v) { return __uint_as_float((unsigned)(v & 0xFFFFFFFFull)); }
__device__ __forceinline__ float hi_f(ull v) { return __uint_as_float((unsigned)(v >> 32)); }

// ---------------------------------------------------------------------------
// Static device scratch
// ---------------------------------------------------------------------------
__device__ float g_xz[(size_t)MTOT * G4];     // 256 MB
__device__ float g_seq1[(size_t)MTOT * HH];   // 64 MB
__device__ float g_hbuf[2][BB * HH];
__device__ float g_Wp[(size_t)HH * G4];
__device__ float g_Up[(size_t)HH * G4];
__device__ float g_bp[G4];
__device__ unsigned g_bar;

// ---------------------------------------------------------------------------
// Permute weights into gate-interleaved layout: dst[k][u*4+g] = src[k][g*H+u]
// ---------------------------------------------------------------------------
__global__ void permute_gates(const float* __restrict__ src, int K, int dst_sel)
{
    float* dst = (dst_sel == 0) ? g_Wp : (dst_sel == 1) ? g_Up : g_bp;
    int idx = blockIdx.x * blockDim.x + threadIdx.x;
    int total = K * G4;
    if (idx >= total) return;
    int k   = idx >> 12;
    int col = idx & 4095;
    int u   = col >> 2;
    int g   = col & 3;
    dst[idx] = src[(size_t)k * G4 + g * HH + u];
}

__global__ void zero_hc()
{
    int idx = blockIdx.x * blockDim.x + threadIdx.x;
    if (idx < BB * HH) g_hbuf[0][idx] = 0.f;
    if (idx == 0) g_bar = 0u;
}

// ---------------------------------------------------------------------------
// Big GEMM with FFMA2 (column-pair packing) + double-buffered smem tiles.
// out[m][n] = sum_k A[m][k]*Wp[k][n] + bp[n];   128x128x16 tiles, 256 thr.
// 1 CTA/SM (heavy regs) -> register-prefetch double buffering hides GMEM.
// ---------------------------------------------------------------------------
template<int MODE>
__global__ __launch_bounds__(256) void gemm_big(const float* __restrict__ Ain, int K)
{
    __shared__ float As[2][16][136];   // transposed: As[buf][k][m]
    __shared__ float Bs[2][16][136];   // Bs[buf][k][n]

    const int tid  = threadIdx.x;
    const int tx   = tid & 15;
    const int ty   = tid >> 4;
    const int row0 = blockIdx.y * 128;
    const int n0   = blockIdx.x * 128;

    const float* A = (MODE == 0) ? Ain : (const float*)g_seq1;

    // A source pointers for this thread's 2 float4 loads
    const int am0 = tid >> 2, aq0 = (tid & 3) * 4;
    const int am1 = (tid + 256) >> 2, aq1 = (tid & 3) * 4;
    const float *ap0, *ap1;
    {
        int mg0 = row0 + am0, mg1 = row0 + am1;
        if (MODE == 0) {
            ap0 = A + ((size_t)((mg0 & 63) * TT + (mg0 >> 6))) * DD;
            ap1 = A + ((size_t)((mg1 & 63) * TT + (mg1 >> 6))) * DD;
        } else {
            ap0 = A + (size_t)mg0 * K;
            ap1 = A + (size_t)mg1 * K;
        }
    }
    const int bk0 = tid >> 5, bq0 = (tid & 31) * 4;
    const int bk1 = (tid + 256) >> 5, bq1 = (tid & 31) * 4;

    // accumulators: 8 rows x 4 column-pairs, init with bias
    ull acc[8][4];
    {
        float b0 = g_bp[n0 + tx * 4 + 0], b1 = g_bp[n0 + tx * 4 + 1];
        float b2 = g_bp[n0 + tx * 4 + 2], b3 = g_bp[n0 + tx * 4 + 3];
        float b4 = g_bp[n0 + 64 + tx * 4 + 0], b5 = g_bp[n0 + 64 + tx * 4 + 1];
        float b6 = g_bp[n0 + 64 + tx * 4 + 2], b7 = g_bp[n0 + 64 + tx * 4 + 3];
        ull p0 = pack2(b0, b1), p1 = pack2(b2, b3), p2 = pack2(b4, b5), p3 = pack2(b6, b7);
#pragma unroll
        for (int r = 0; r < 8; r++) { acc[r][0] = p0; acc[r][1] = p1; acc[r][2] = p2; acc[r][3] = p3; }
    }

    // preload tile 0
    float4 pa0 = *(const float4*)(ap0 + aq0);
    float4 pa1 = *(const float4*)(ap1 + aq1);
    float4 pb0 = *(const float4*)(g_Wp + (size_t)bk0 * G4 + n0 + bq0);
    float4 pb1 = *(const float4*)(g_Wp + (size_t)bk1 * G4 + n0 + bq1);
    As[0][aq0 + 0][am0] = pa0.x; As[0][aq0 + 1][am0] = pa0.y;
    As[0][aq0 + 2][am0] = pa0.z; As[0][aq0 + 3][am0] = pa0.w;
    As[0][aq1 + 0][am1] = pa1.x; As[0][aq1 + 1][am1] = pa1.y;
    As[0][aq1 + 2][am1] = pa1.z; As[0][aq1 + 3][am1] = pa1.w;
    *(float4*)&Bs[0][bk0][bq0] = pb0;
    *(float4*)&Bs[0][bk1][bq1] = pb1;
    __syncthreads();

    int buf = 0;
    for (int k0 = 0; k0 < K; k0 += 16) {
        const bool more = (k0 + 16) < K;
        if (more) {
            pa0 = *(const float4*)(ap0 + k0 + 16 + aq0);
            pa1 = *(const float4*)(ap1 + k0 + 16 + aq1);
            pb0 = *(const float4*)(g_Wp + (size_t)(k0 + 16 + bk0) * G4 + n0 + bq0);
            pb1 = *(const float4*)(g_Wp + (size_t)(k0 + 16 + bk1) * G4 + n0 + bq1);
        }
#pragma unroll
        for (int k = 0; k < 16; k++) {
            ulonglong2 blo = *(const ulonglong2*)&Bs[buf][k][tx * 4];
            ulonglong2 bhi = *(const ulonglong2*)&Bs[buf][k][64 + tx * 4];
            float a[8];
            *(float4*)&a[0] = *(const float4*)&As[buf][k][ty * 4];
            *(float4*)&a[4] = *(const float4*)&As[buf][k][64 + ty * 4];
#pragma unroll
            for (int r = 0; r < 8; r++) {
                ull ap = pack_dup(a[r]);
                ffma2(acc[r][0], ap, blo.x);
                ffma2(acc[r][1], ap, blo.y);
                ffma2(acc[r][2], ap, bhi.x);
                ffma2(acc[r][3], ap, bhi.y);
            }
        }
        if (more) {
            int nb = buf ^ 1;
            As[nb][aq0 + 0][am0] = pa0.x; As[nb][aq0 + 1][am0] = pa0.y;
            As[nb][aq0 + 2][am0] = pa0.z; As[nb][aq0 + 3][am0] = pa0.w;
            As[nb][aq1 + 0][am1] = pa1.x; As[nb][aq1 + 1][am1] = pa1.y;
            As[nb][aq1 + 2][am1] = pa1.z; As[nb][aq1 + 3][am1] = pa1.w;
            *(float4*)&Bs[nb][bk0][bq0] = pb0;
            *(float4*)&Bs[nb][bk1][bq1] = pb1;
        }
        __syncthreads();
        buf ^= 1;
    }

#pragma unroll
    for (int r = 0; r < 8; r++) {
        int m = row0 + ((r < 4) ? (ty * 4 + r) : (64 + ty * 4 + (r - 4)));
        float* op = g_xz + (size_t)m * G4 + n0;
        float4 v0 = make_float4(lo_f(acc[r][0]), hi_f(acc[r][0]),
                                lo_f(acc[r][1]), hi_f(acc[r][1]));
        float4 v1 = make_float4(lo_f(acc[r][2]), hi_f(acc[r][2]),
                                lo_f(acc[r][3]), hi_f(acc[r][3]));
        *(float4*)(op + tx * 4)      = v0;
        *(float4*)(op + 64 + tx * 4) = v1;
    }
}

// ---------------------------------------------------------------------------
// Persistent recurrence kernel, v2:
//   - warp geometry: lanes span 4 row-groups x 8 cols -> hv LDS.128 hits 4
//     distinct bank-quads (sH row stride 36) = 1 crossbar cycle, not 4
//   - FFMA2 packed over k-pairs; U repacked pair-interleaved in smem
//   - c in registers, grid barrier between steps (1 CTA/SM x 128)
// ---------------------------------------------------------------------------
#define RST 36                              // sH row stride (floats)
#define SM_U 0                              // 512 pairs * 64 = 32768 floats
#define SM_H 32768                          // 2 * 64*36 = 4608
#define SM_Z (32768 + 4608)                 // 64*33 = 2112
#define SM_TOT_FLOATS (32768 + 4608 + 2112) // 39488 -> 157,952 B

__global__ __launch_bounds__(256) void lstm_layer_persist(int layer)
{
    extern __shared__ float sm[];
    float* sU2 = sm + SM_U;   // [pair][col*2 + e]
    float* sH  = sm + SM_H;   // [2][64*RST]
    float* sZ  = sm + SM_Z;   // [64*33]

    const int tid = threadIdx.x;
    const int l   = tid & 31;
    const int w   = tid >> 5;
    const int col = (w & 3) * 8 + (l & 7);          // 0..31
    const int rg  = (l >> 3) + ((w >> 2) << 2);     // 0..7  (thread rows: rg+8r)
    const int c0  = blockIdx.x * 32;                // column base in [0,4096)

    // ---- repack U slice into k-pair-interleaved smem (once per layer) ----
    for (int i = tid; i < 32768; i += 256) {
        int k = i >> 5, cc = i & 31;                // read coalesced over cc
        sU2[(k >> 1) * 64 + cc * 2 + (k & 1)] = g_Up[(size_t)k * G4 + c0 + cc];
    }

    float creg0 = 0.f, creg1 = 0.f;

    const int hm0 = tid >> 3,         hq0 = (tid & 7) * 4;
    const int hm1 = (tid + 256) >> 3, hq1 = (tid & 7) * 4;

    __syncthreads();

    unsigned bar_target = 0;
    volatile unsigned* barp = &g_bar;

    for (int t = 0; t < TT; t++) {
        const float* xz_t   = g_xz + (size_t)t * BB * G4;
        const float* h_prev = g_hbuf[t & 1];
        float*       h_new  = g_hbuf[(t + 1) & 1];

        // acc init = xz (bias folded in); pack as {xz, 0}
        ull acc[8];
#pragma unroll
        for (int r = 0; r < 8; r++)
            acc[r] = (ull)__float_as_uint(xz_t[(size_t)(rg + 8 * r) * G4 + c0 + col]);

        // preload h chunk 0 (L2 reads — L1 stale across steps)
        float4 pre0 = __ldcg((const float4*)(h_prev + (size_t)hm0 * HH + hq0));
        float4 pre1 = __ldcg((const float4*)(h_prev + (size_t)hm1 * HH + hq1));
        *(float4*)&sH[hm0 * RST + hq0] = pre0;
        *(float4*)&sH[hm1 * RST + hq1] = pre1;
        __syncthreads();

        int buf = 0;
        for (int k0 = 0; k0 < HH; k0 += 32) {
            const bool more = (k0 + 32) < HH;
            if (more) {
                pre0 = __ldcg((const float4*)(h_prev + (size_t)hm0 * HH + k0 + 32 + hq0));
                pre1 = __ldcg((const float4*)(h_prev + (size_t)hm1 * HH + k0 + 32 + hq1));
            }
            const float* hb  = &sH[buf * (64 * RST)];
            const float* ub2 = &sU2[(k0 >> 1) * 64];
#pragma unroll
            for (int j = 0; j < 8; j++) {
                ull u0 = *(const ull*)&ub2[(2 * j)     * 64 + col * 2];
                ull u1 = *(const ull*)&ub2[(2 * j + 1) * 64 + col * 2];
#pragma unroll
                for (int r = 0; r < 8; r++) {
                    ulonglong2 hv = *(const ulonglong2*)&hb[(rg + 8 * r) * RST + j * 4];
                    ffma2(acc[r], hv.x, u0);
                    ffma2(acc[r], hv.y, u1);
                }
            }
            if (more) {
                float* nb = &sH[(buf ^ 1) * (64 * RST)];
                *(float4*)&nb[hm0 * RST + hq0] = pre0;
                *(float4*)&nb[hm1 * RST + hq1] = pre1;
            }
            buf ^= 1;
            __syncthreads();
        }

        // reduce pairs, stage z tile
#pragma unroll
        for (int r = 0; r < 8; r++)
            sZ[(rg + 8 * r) * 33 + col] = lo_f(acc[r]) + hi_f(acc[r]);
        __syncthreads();

        // gates (fixed thread->cell map so c can live in registers)
#pragma unroll
        for (int p = 0; p < 2; p++) {
            int item = tid + p * 256;          // 512 (m, unit) items
            int m = item >> 3, u = item & 7;
            float zi = sZ[m * 33 + u * 4 + 0];
            float zf = sZ[m * 33 + u * 4 + 1];
            float zg = sZ[m * 33 + u * 4 + 2];
            float zo = sZ[m * 33 + u * 4 + 3];
            float cold = (p == 0) ? creg0 : creg1;
            float si = 1.f / (1.f + __expf(-zi));
            float sf = 1.f / (1.f + __expf(-zf));
            float so = 1.f / (1.f + __expf(-zo));
            float tg = tanhf(zg);
            float cn = sf * cold + si * tg;
            float hn = so * tanhf(cn);
            if (p == 0) creg0 = cn; else creg1 = cn;
            int uu  = (c0 >> 2) + u;
            int idx = m * HH + uu;
            h_new[idx] = hn;
            if (layer == 0)
                g_seq1[(size_t)t * BB * HH + idx] = hn;
        }

        if (t < TT - 1) {
            __threadfence();
            __syncthreads();
            bar_target += 128;
            if (tid == 0) {
                atomicAdd(&g_bar, 1u);
                while (*barp < bar_target) { }
            }
            __syncthreads();
        }
    }
}

// ---------------------------------------------------------------------------
// Final dense
// ---------------------------------------------------------------------------
__global__ void dense_out(const float* __restrict__ Wd, const float* __restrict__ bd,
                          float* __restrict__ out)
{
    int b = blockIdx.x;
    int o = threadIdx.x;
    const float* hp = g_hbuf[0] + (size_t)b * HH;   // T even -> final h in buf 0
    float acc = bd[o];
#pragma unroll 8
    for (int k = 0; k < HH; k++)
        acc += hp[k] * Wd[(size_t)k * OO + o];
    out[(size_t)b * OO + o] = acc;
}

// ---------------------------------------------------------------------------
// Launch sequence
// ---------------------------------------------------------------------------
extern "C" void kernel_launch(void* const* d_in, const int* in_sizes, int n_in,
                              void* d_out, int out_size)
{
    const float* x  = (const float*)d_in[0];
    const float* W1 = (const float*)d_in[1];
    const float* U1 = (const float*)d_in[2];
    const float* b1 = (const float*)d_in[3];
    const float* W2 = (const float*)d_in[4];
    const float* U2 = (const float*)d_in[5];
    const float* b2 = (const float*)d_in[6];
    const float* Wd = (const float*)d_in[7];
    const float* bd = (const float*)d_in[8];
    float* out = (float*)d_out;

    const int smem_bytes = SM_TOT_FLOATS * sizeof(float);   // 157,952 B
    cudaFuncSetAttribute(lstm_layer_persist,
                         cudaFuncAttributeMaxDynamicSharedMemorySize, smem_bytes);

    dim3 gemm_grid(G4 / 128, MTOT / 128);

    // ---- Layer 1 ----
    permute_gates<<<(DD * G4 + 255) / 256, 256>>>(W1, DD, 0);
    permute_gates<<<(HH * G4 + 255) / 256, 256>>>(U1, HH, 1);
    permute_gates<<<(G4 + 255) / 256, 256>>>(b1, 1, 2);
    zero_hc<<<(BB * HH + 255) / 256, 256>>>();
    gemm_big<0><<<gemm_grid, 256>>>(x, DD);
    lstm_layer_persist<<<128, 256, smem_bytes>>>(0);

    // ---- Layer 2 ----
    permute_gates<<<(HH * G4 + 255) / 256, 256>>>(W2, HH, 0);
    permute_gates<<<(HH * G4 + 255) / 256, 256>>>(U2, HH, 1);
    permute_gates<<<(G4 + 255) / 256, 256>>>(b2, 1, 2);
    zero_hc<<<(BB * HH + 255) / 256, 256>>>();
    gemm_big<1><<<gemm_grid, 256>>>(nullptr, HH);
    lstm_layer_persist<<<128, 256, smem_bytes>>>(1);

    // ---- Dense head ----
    dense_out<<<BB, OO>>>(Wd, bd, out);
}

// round 8
// speedup vs baseline: 1.1687x; 1.0008x over previous
#include <cuda_runtime.h>
#include <math.h>

// Problem constants
#define BB 64
#define TT 256
#define DD 512
#define HH 1024         // H1 == H2
#define G4 4096         // 4*H
#define OO 512
#define MTOT (BB*TT)    // 16384

typedef unsigned long long ull;

// ---------------------------------------------------------------------------
// f32x2 packed-FMA helpers (sm_103a FFMA2)
// ---------------------------------------------------------------------------
__device__ __forceinline__ void ffma2(ull& d, ull a, ull b) {
    asm("fma.rn.f32x2 %0, %1, %2, %0;" : "+l"(d) : "l"(a), "l"(b));
}
__device__ __forceinline__ ull pack_dup(float x) {
    ull r; asm("mov.b64 %0, {%1, %1};" : "=l"(r) : "f"(x)); return r;
}
__device__ __forceinline__ ull pack2(float lo, float hi) {
    ull r; asm("mov.b64 %0, {%1, %2};" : "=l"(r) : "f"(lo), "f"(hi)); return r;
}
__device__ __forceinline__ float lo_f(ull v) { return __uint_as_float((unsigned)(v & 0xFFFFFFFFull)); }
__device__ __forceinline__ float hi_f(ull v) { return __uint_as_float((unsigned)(v >> 32)); }

// ---------------------------------------------------------------------------
// Static device scratch
// ---------------------------------------------------------------------------
__device__ float g_xz[(size_t)MTOT * G4];     // 256 MB  z-pre (natural layout)
__device__ float g_seq1[(size_t)MTOT * HH];   // 64 MB   layer-1 h sequence
__device__ float g_hbuf[2][BB * HH];
__device__ unsigned g_bar;

// ---------------------------------------------------------------------------
// Zero h0 and the grid-barrier counter before each recurrence.
// (Called twice in a row once, as a harmless spacer for ncu launch indexing.)
// ---------------------------------------------------------------------------
__global__ void zero_hc()
{
    int idx = blockIdx.x * blockDim.x + threadIdx.x;
    if (idx < BB * HH) g_hbuf[0][idx] = 0.f;
    if (idx == 0) g_bar = 0u;
}

// ---------------------------------------------------------------------------
// Big GEMM (natural column layout, raw W/b inputs):
//   g_xz[m][n] = sum_k A[m][k]*W[k][n] + b[n],  m = t*B + bb
//   MODE 0: A = x [b][t][d] (K=512);  MODE 1: A = g_seq1 [m][k] (K=1024)
// 128x128x16 tiles, 256 thr, FFMA2 column pairs, double-buffered smem.
// ---------------------------------------------------------------------------
template<int MODE>
__global__ __launch_bounds__(256) void gemm_big(const float* __restrict__ Ain,
                                                const float* __restrict__ W,
                                                const float* __restrict__ bias,
                                                int K)
{
    __shared__ float As[2][16][136];   // As[buf][k][m] (transposed)
    __shared__ float Bs[2][16][136];   // Bs[buf][k][n]

    const int tid  = threadIdx.x;
    const int tx   = tid & 15;
    const int ty   = tid >> 4;
    const int row0 = blockIdx.y * 128;
    const int n0   = blockIdx.x * 128;

    const float* A = (MODE == 0) ? Ain : (const float*)g_seq1;

    const int am0 = tid >> 2, aq0 = (tid & 3) * 4;
    const int am1 = (tid + 256) >> 2, aq1 = (tid & 3) * 4;
    const float *ap0, *ap1;
    {
        int mg0 = row0 + am0, mg1 = row0 + am1;
        if (MODE == 0) {
            ap0 = A + ((size_t)((mg0 & 63) * TT + (mg0 >> 6))) * DD;
            ap1 = A + ((size_t)((mg1 & 63) * TT + (mg1 >> 6))) * DD;
        } else {
            ap0 = A + (size_t)mg0 * K;
            ap1 = A + (size_t)mg1 * K;
        }
    }
    const int bk0 = tid >> 5, bq0 = (tid & 31) * 4;
    const int bk1 = (tid + 256) >> 5, bq1 = (tid & 31) * 4;

    ull acc[8][4];
    {
        float b0 = bias[n0 + tx * 4 + 0], b1 = bias[n0 + tx * 4 + 1];
        float b2 = bias[n0 + tx * 4 + 2], b3 = bias[n0 + tx * 4 + 3];
        float b4 = bias[n0 + 64 + tx * 4 + 0], b5 = bias[n0 + 64 + tx * 4 + 1];
        float b6 = bias[n0 + 64 + tx * 4 + 2], b7 = bias[n0 + 64 + tx * 4 + 3];
        ull p0 = pack2(b0, b1), p1 = pack2(b2, b3), p2 = pack2(b4, b5), p3 = pack2(b6, b7);
#pragma unroll
        for (int r = 0; r < 8; r++) { acc[r][0] = p0; acc[r][1] = p1; acc[r][2] = p2; acc[r][3] = p3; }
    }

    // preload tile 0
    float4 pa0 = *(const float4*)(ap0 + aq0);
    float4 pa1 = *(const float4*)(ap1 + aq1);
    float4 pb0 = *(const float4*)(W + (size_t)bk0 * G4 + n0 + bq0);
    float4 pb1 = *(const float4*)(W + (size_t)bk1 * G4 + n0 + bq1);
    As[0][aq0 + 0][am0] = pa0.x; As[0][aq0 + 1][am0] = pa0.y;
    As[0][aq0 + 2][am0] = pa0.z; As[0][aq0 + 3][am0] = pa0.w;
    As[0][aq1 + 0][am1] = pa1.x; As[0][aq1 + 1][am1] = pa1.y;
    As[0][aq1 + 2][am1] = pa1.z; As[0][aq1 + 3][am1] = pa1.w;
    *(float4*)&Bs[0][bk0][bq0] = pb0;
    *(float4*)&Bs[0][bk1][bq1] = pb1;
    __syncthreads();

    int buf = 0;
    for (int k0 = 0; k0 < K; k0 += 16) {
        const bool more = (k0 + 16) < K;
        if (more) {
            pa0 = *(const float4*)(ap0 + k0 + 16 + aq0);
            pa1 = *(const float4*)(ap1 + k0 + 16 + aq1);
            pb0 = *(const float4*)(W + (size_t)(k0 + 16 + bk0) * G4 + n0 + bq0);
            pb1 = *(const float4*)(W + (size_t)(k0 + 16 + bk1) * G4 + n0 + bq1);
        }
#pragma unroll
        for (int k = 0; k < 16; k++) {
            ulonglong2 blo = *(const ulonglong2*)&Bs[buf][k][tx * 4];
            ulonglong2 bhi = *(const ulonglong2*)&Bs[buf][k][64 + tx * 4];
            float a[8];
            *(float4*)&a[0] = *(const float4*)&As[buf][k][ty * 4];
            *(float4*)&a[4] = *(const float4*)&As[buf][k][64 + ty * 4];
#pragma unroll
            for (int r = 0; r < 8; r++) {
                ull ap = pack_dup(a[r]);
                ffma2(acc[r][0], ap, blo.x);
                ffma2(acc[r][1], ap, blo.y);
                ffma2(acc[r][2], ap, bhi.x);
                ffma2(acc[r][3], ap, bhi.y);
            }
        }
        if (more) {
            int nb = buf ^ 1;
            As[nb][aq0 + 0][am0] = pa0.x; As[nb][aq0 + 1][am0] = pa0.y;
            As[nb][aq0 + 2][am0] = pa0.z; As[nb][aq0 + 3][am0] = pa0.w;
            As[nb][aq1 + 0][am1] = pa1.x; As[nb][aq1 + 1][am1] = pa1.y;
            As[nb][aq1 + 2][am1] = pa1.z; As[nb][aq1 + 3][am1] = pa1.w;
            *(float4*)&Bs[nb][bk0][bq0] = pb0;
            *(float4*)&Bs[nb][bk1][bq1] = pb1;
        }
        __syncthreads();
        buf ^= 1;
    }

#pragma unroll
    for (int r = 0; r < 8; r++) {
        int m = row0 + ((r < 4) ? (ty * 4 + r) : (64 + ty * 4 + (r - 4)));
        float* op = g_xz + (size_t)m * G4 + n0;
        float4 v0 = make_float4(lo_f(acc[r][0]), hi_f(acc[r][0]),
                                lo_f(acc[r][1]), hi_f(acc[r][1]));
        float4 v1 = make_float4(lo_f(acc[r][2]), hi_f(acc[r][2]),
                                lo_f(acc[r][3]), hi_f(acc[r][3]));
        *(float4*)(op + tx * 4)      = v0;
        *(float4*)(op + 64 + tx * 4) = v1;
    }
}

// ---------------------------------------------------------------------------
// Persistent recurrence kernel, v3: 512 threads (16 warps -> 4/SMSP for
// latency hiding). CTA cb owns units u0=cb*8..+7, i.e. natural z columns
// {g*1024 + u0 + j}. U consumed directly from raw input (no permute kernel);
// repacked k-pair-interleaved in smem once per layer. c in registers
// (1 cell/thread). Grid barrier between steps. FFMA2 inner loop,
// conflict-free smem geometry (4 row-groups x 8 cols per warp, RST=36).
// ---------------------------------------------------------------------------
#define RST 36
#define SM_U 0                              // 512 pairs * 64 = 32768 floats
#define SM_H 32768                          // 2 * 64*36 = 4608
#define SM_Z (32768 + 4608)                 // 64*33 = 2112
#define SM_TOT_FLOATS (32768 + 4608 + 2112) // 157,952 B

__global__ __launch_bounds__(512) void lstm_layer_persist(const float* __restrict__ U,
                                                          int layer)
{
    extern __shared__ float sm[];
    float* sU2 = sm + SM_U;
    float* sH  = sm + SM_H;
    float* sZ  = sm + SM_Z;

    const int tid = threadIdx.x;
    const int l   = tid & 31;
    const int w   = tid >> 5;                       // 0..15
    const int c   = (w & 3) * 8 + (l & 7);          // local col 0..31
    const int rg  = (l >> 3) + ((w >> 2) << 2);     // row-group 0..15
    const int u0  = blockIdx.x * 8;                 // unit base
    // global z column for local col c: gate block + unit
    const int gcol = ((c >> 3) << 10) + u0 + (c & 7);

    // ---- repack U slice k-pair-interleaved into smem (once per layer) ----
    for (int i = tid; i < 32768; i += 512) {
        int k = i >> 5, cc = i & 31;
        int gc = ((cc >> 3) << 10) + u0 + (cc & 7);
        sU2[(k >> 1) * 64 + cc * 2 + (k & 1)] = U[(size_t)k * G4 + gc];
    }

    float creg = 0.f;                               // 1 cell per thread

    const int hm = tid >> 3, hq = (tid & 7) * 4;    // h-chunk staging (1 float4/thr)

    __syncthreads();

    unsigned bar_target = 0;
    volatile unsigned* barp = &g_bar;

    for (int t = 0; t < TT; t++) {
        const float* xz_t   = g_xz + (size_t)t * BB * G4;
        const float* h_prev = g_hbuf[t & 1];
        float*       h_new  = g_hbuf[(t + 1) & 1];

        // acc init = z-pre (bias folded in); pack {xz, 0}
        ull acc[4];
#pragma unroll
        for (int r = 0; r < 4; r++)
            acc[r] = (ull)__float_as_uint(__ldg(xz_t + (size_t)(rg + 16 * r) * G4 + gcol));

        // preload h chunk 0 (L2 reads — L1 stale across steps)
        float4 pre = __ldcg((const float4*)(h_prev + (size_t)hm * HH + hq));
        *(float4*)&sH[hm * RST + hq] = pre;
        __syncthreads();

        int buf = 0;
        for (int k0 = 0; k0 < HH; k0 += 32) {
            const bool more = (k0 + 32) < HH;
            if (more)
                pre = __ldcg((const float4*)(h_prev + (size_t)hm * HH + k0 + 32 + hq));
            const float* hb  = &sH[buf * (64 * RST)];
            const float* ub2 = &sU2[(k0 >> 1) * 64];
#pragma unroll
            for (int j = 0; j < 8; j++) {
                ull uA = *(const ull*)&ub2[(2 * j)     * 64 + c * 2];
                ull uB = *(const ull*)&ub2[(2 * j + 1) * 64 + c * 2];
#pragma unroll
                for (int r = 0; r < 4; r++) {
                    ulonglong2 hv = *(const ulonglong2*)&hb[(rg + 16 * r) * RST + j * 4];
                    ffma2(acc[r], hv.x, uA);
                    ffma2(acc[r], hv.y, uB);
                }
            }
            if (more) {
                float* nb = &sH[(buf ^ 1) * (64 * RST)];
                *(float4*)&nb[hm * RST + hq] = pre;
            }
            buf ^= 1;
            __syncthreads();
        }

        // reduce pairs, stage z tile
#pragma unroll
        for (int r = 0; r < 4; r++)
            sZ[(rg + 16 * r) * 33 + c] = lo_f(acc[r]) + hi_f(acc[r]);
        __syncthreads();

        // gates: thread -> cell (m, jj); gate g at local col g*8+jj
        {
            int m  = tid >> 3, jj = tid & 7;
            float zi = sZ[m * 33 +  0 + jj];
            float zf = sZ[m * 33 +  8 + jj];
            float zg = sZ[m * 33 + 16 + jj];
            float zo = sZ[m * 33 + 24 + jj];
            float si = 1.f / (1.f + __expf(-zi));
            float sf = 1.f / (1.f + __expf(-zf));
            float so = 1.f / (1.f + __expf(-zo));
            float tg = tanhf(zg);
            float cn = sf * creg + si * tg;
            float hn = so * tanhf(cn);
            creg = cn;
            int idx = m * HH + u0 + jj;
            h_new[idx] = hn;
            if (layer == 0)
                g_seq1[(size_t)t * BB * HH + idx] = hn;
        }

        if (t < TT - 1) {
            __threadfence();
            __syncthreads();
            bar_target += 128;
            if (tid == 0) {
                atomicAdd(&g_bar, 1u);
                while (*barp < bar_target) { }
            }
            __syncthreads();
        }
    }
}

// ---------------------------------------------------------------------------
// Final dense
// ---------------------------------------------------------------------------
__global__ void dense_out(const float* __restrict__ Wd, const float* __restrict__ bd,
                          float* __restrict__ out)
{
    int b = blockIdx.x;
    int o = threadIdx.x;
    const float* hp = g_hbuf[0] + (size_t)b * HH;   // T even -> final h in buf 0
    float acc = bd[o];
#pragma unroll 8
    for (int k = 0; k < HH; k++)
        acc += hp[k] * Wd[(size_t)k * OO + o];
    out[(size_t)b * OO + o] = acc;
}

// ---------------------------------------------------------------------------
// Launch sequence. Order chosen so ncu's capture (launch index 3 of this
// sequence, per rounds 5-7 evidence) lands on lstm_layer_persist.
// ---------------------------------------------------------------------------
extern "C" void kernel_launch(void* const* d_in, const int* in_sizes, int n_in,
                              void* d_out, int out_size)
{
    const float* x  = (const float*)d_in[0];
    const float* W1 = (const float*)d_in[1];
    const float* U1 = (const float*)d_in[2];
    const float* b1 = (const float*)d_in[3];
    const float* W2 = (const float*)d_in[4];
    const float* U2 = (const float*)d_in[5];
    const float* b2 = (const float*)d_in[6];
    const float* Wd = (const float*)d_in[7];
    const float* bd = (const float*)d_in[8];
    float* out = (float*)d_out;

    const int smem_bytes = SM_TOT_FLOATS * sizeof(float);   // 157,952 B
    cudaFuncSetAttribute(lstm_layer_persist,
                         cudaFuncAttributeMaxDynamicSharedMemorySize, smem_bytes);

    dim3 gemm_grid(G4 / 128, MTOT / 128);

    // ---- Layer 1 ----
    gemm_big<0><<<gemm_grid, 256>>>(x, W1, b1, DD);          // launch 0
    zero_hc<<<(BB * HH + 255) / 256, 256>>>();               // launch 1
    zero_hc<<<(BB * HH + 255) / 256, 256>>>();               // launch 2 (spacer)
    lstm_layer_persist<<<128, 512, smem_bytes>>>(U1, 0);     // launch 3 <- profiled

    // ---- Layer 2 ----
    gemm_big<1><<<gemm_grid, 256>>>(nullptr, W2, b2, HH);    // launch 4
    zero_hc<<<(BB * HH + 255) / 256, 256>>>();               // launch 5
    lstm_layer_persist<<<128, 512, smem_bytes>>>(U2, 1);     // launch 6

    // ---- Dense head ----
    dense_out<<<BB, OO>>>(Wd, bd, out);                      // launch 7
}

// round 10
// speedup vs baseline: 1.9009x; 1.6266x over previous
#include <cuda_runtime.h>
#include <cuda_bf16.h>
#include <math.h>
#include <stdint.h>

// Problem constants
#define BB 64
#define TT 256
#define DD 512
#define HH 1024         // H1 == H2
#define G4 4096         // 4*H
#define OO 512
#define MTOT (BB*TT)    // 16384

typedef unsigned long long ull;

// ---------------------------------------------------------------------------
// f32x2 packed-FMA helpers (sm_103a FFMA2) — used by the xz GEMM
// ---------------------------------------------------------------------------
__device__ __forceinline__ void ffma2(ull& d, ull a, ull b) {
    asm("fma.rn.f32x2 %0, %1, %2, %0;" : "+l"(d) : "l"(a), "l"(b));
}
__device__ __forceinline__ ull pack_dup(float x) {
    ull r; asm("mov.b64 %0, {%1, %1};" : "=l"(r) : "f"(x)); return r;
}
__device__ __forceinline__ ull pack2(float lo, float hi) {
    ull r; asm("mov.b64 %0, {%1, %2};" : "=l"(r) : "f"(lo), "f"(hi)); return r;
}
__device__ __forceinline__ float lo_f(ull v) { return __uint_as_float((unsigned)(v & 0xFFFFFFFFull)); }
__device__ __forceinline__ float hi_f(ull v) { return __uint_as_float((unsigned)(v >> 32)); }

// ---------------------------------------------------------------------------
// bf16 split helpers
// ---------------------------------------------------------------------------
__device__ __forceinline__ unsigned pk_bf(float a, float b) {
    unsigned short ua = __bfloat16_as_ushort(__float2bfloat16_rn(a));
    unsigned short ub = __bfloat16_as_ushort(__float2bfloat16_rn(b));
    return (unsigned)ua | ((unsigned)ub << 16);
}
__device__ __forceinline__ float bf_res(float x) {
    return x - __bfloat162float(__float2bfloat16_rn(x));
}

// mma.sync m16n8k16 bf16 (baseline PTX, sm_80+, valid on compute_103)
__device__ __forceinline__ void mma_bf16(float* d,
                                         uint32_t a0, uint32_t a1, uint32_t a2, uint32_t a3,
                                         uint32_t b0, uint32_t b1) {
    asm volatile(
        "mma.sync.aligned.m16n8k16.row.col.f32.bf16.bf16.f32 "
        "{%0,%1,%2,%3}, {%4,%5,%6,%7}, {%8,%9}, {%0,%1,%2,%3};"
        : "+f"(d[0]), "+f"(d[1]), "+f"(d[2]), "+f"(d[3])
        : "r"(a0), "r"(a1), "r"(a2), "r"(a3), "r"(b0), "r"(b1));
}

// ---------------------------------------------------------------------------
// Static device scratch
// ---------------------------------------------------------------------------
__device__ float g_xz[(size_t)MTOT * G4];     // 256 MB  z-pre (natural layout)
__device__ float g_seq1[(size_t)MTOT * HH];   // 64 MB   layer-1 h sequence
__device__ float g_hbuf[2][BB * HH];
__device__ unsigned g_bar8[8];                // split grid-barrier counters

__global__ void zero_hc()
{
    int idx = blockIdx.x * blockDim.x + threadIdx.x;
    if (idx < BB * HH) g_hbuf[0][idx] = 0.f;
    if (idx < 8) g_bar8[idx] = 0u;
}

// ---------------------------------------------------------------------------
// Big GEMM (fp32 FFMA2, known good): g_xz[m][n] = sum_k A[m][k]*W[k][n] + b[n]
// ---------------------------------------------------------------------------
template<int MODE>
__global__ __launch_bounds__(256) void gemm_big(const float* __restrict__ Ain,
                                                const float* __restrict__ W,
                                                const float* __restrict__ bias,
                                                int K)
{
    __shared__ float As[2][16][136];
    __shared__ float Bs[2][16][136];

    const int tid  = threadIdx.x;
    const int tx   = tid & 15;
    const int ty   = tid >> 4;
    const int row0 = blockIdx.y * 128;
    const int n0   = blockIdx.x * 128;

    const float* A = (MODE == 0) ? Ain : (const float*)g_seq1;

    const int am0 = tid >> 2, aq0 = (tid & 3) * 4;
    const int am1 = (tid + 256) >> 2, aq1 = (tid & 3) * 4;
    const float *ap0, *ap1;
    {
        int mg0 = row0 + am0, mg1 = row0 + am1;
        if (MODE == 0) {
            ap0 = A + ((size_t)((mg0 & 63) * TT + (mg0 >> 6))) * DD;
            ap1 = A + ((size_t)((mg1 & 63) * TT + (mg1 >> 6))) * DD;
        } else {
            ap0 = A + (size_t)mg0 * K;
            ap1 = A + (size_t)mg1 * K;
        }
    }
    const int bk0 = tid >> 5, bq0 = (tid & 31) * 4;
    const int bk1 = (tid + 256) >> 5, bq1 = (tid & 31) * 4;

    ull acc[8][4];
    {
        float b0 = bias[n0 + tx * 4 + 0], b1 = bias[n0 + tx * 4 + 1];
        float b2 = bias[n0 + tx * 4 + 2], b3 = bias[n0 + tx * 4 + 3];
        float b4 = bias[n0 + 64 + tx * 4 + 0], b5 = bias[n0 + 64 + tx * 4 + 1];
        float b6 = bias[n0 + 64 + tx * 4 + 2], b7 = bias[n0 + 64 + tx * 4 + 3];
        ull p0 = pack2(b0, b1), p1 = pack2(b2, b3), p2 = pack2(b4, b5), p3 = pack2(b6, b7);
#pragma unroll
        for (int r = 0; r < 8; r++) { acc[r][0] = p0; acc[r][1] = p1; acc[r][2] = p2; acc[r][3] = p3; }
    }

    float4 pa0 = *(const float4*)(ap0 + aq0);
    float4 pa1 = *(const float4*)(ap1 + aq1);
    float4 pb0 = *(const float4*)(W + (size_t)bk0 * G4 + n0 + bq0);
    float4 pb1 = *(const float4*)(W + (size_t)bk1 * G4 + n0 + bq1);
    As[0][aq0 + 0][am0] = pa0.x; As[0][aq0 + 1][am0] = pa0.y;
    As[0][aq0 + 2][am0] = pa0.z; As[0][aq0 + 3][am0] = pa0.w;
    As[0][aq1 + 0][am1] = pa1.x; As[0][aq1 + 1][am1] = pa1.y;
    As[0][aq1 + 2][am1] = pa1.z; As[0][aq1 + 3][am1] = pa1.w;
    *(float4*)&Bs[0][bk0][bq0] = pb0;
    *(float4*)&Bs[0][bk1][bq1] = pb1;
    __syncthreads();

    int buf = 0;
    for (int k0 = 0; k0 < K; k0 += 16) {
        const bool more = (k0 + 16) < K;
        if (more) {
            pa0 = *(const float4*)(ap0 + k0 + 16 + aq0);
            pa1 = *(const float4*)(ap1 + k0 + 16 + aq1);
            pb0 = *(const float4*)(W + (size_t)(k0 + 16 + bk0) * G4 + n0 + bq0);
            pb1 = *(const float4*)(W + (size_t)(k0 + 16 + bk1) * G4 + n0 + bq1);
        }
#pragma unroll
        for (int k = 0; k < 16; k++) {
            ulonglong2 blo = *(const ulonglong2*)&Bs[buf][k][tx * 4];
            ulonglong2 bhi = *(const ulonglong2*)&Bs[buf][k][64 + tx * 4];
            float a[8];
            *(float4*)&a[0] = *(const float4*)&As[buf][k][ty * 4];
            *(float4*)&a[4] = *(const float4*)&As[buf][k][64 + ty * 4];
#pragma unroll
            for (int r = 0; r < 8; r++) {
                ull ap = pack_dup(a[r]);
                ffma2(acc[r][0], ap, blo.x);
                ffma2(acc[r][1], ap, blo.y);
                ffma2(acc[r][2], ap, bhi.x);
                ffma2(acc[r][3], ap, bhi.y);
            }
        }
        if (more) {
            int nb = buf ^ 1;
            As[nb][aq0 + 0][am0] = pa0.x; As[nb][aq0 + 1][am0] = pa0.y;
            As[nb][aq0 + 2][am0] = pa0.z; As[nb][aq0 + 3][am0] = pa0.w;
            As[nb][aq1 + 0][am1] = pa1.x; As[nb][aq1 + 1][am1] = pa1.y;
            As[nb][aq1 + 2][am1] = pa1.z; As[nb][aq1 + 3][am1] = pa1.w;
            *(float4*)&Bs[nb][bk0][bq0] = pb0;
            *(float4*)&Bs[nb][bk1][bq1] = pb1;
        }
        __syncthreads();
        buf ^= 1;
    }

#pragma unroll
    for (int r = 0; r < 8; r++) {
        int m = row0 + ((r < 4) ? (ty * 4 + r) : (64 + ty * 4 + (r - 4)));
        float* op = g_xz + (size_t)m * G4 + n0;
        float4 v0 = make_float4(lo_f(acc[r][0]), hi_f(acc[r][0]),
                                lo_f(acc[r][1]), hi_f(acc[r][1]));
        float4 v1 = make_float4(lo_f(acc[r][2]), hi_f(acc[r][2]),
                                lo_f(acc[r][3]), hi_f(acc[r][3]));
        *(float4*)(op + tx * 4)      = v0;
        *(float4*)(op + 64 + tx * 4) = v1;
    }
}

// ---------------------------------------------------------------------------
// Persistent mma.sync recurrence. 128 CTAs x 512 thr (16 warps), 1 CTA/SM.
// Per CTA per step: Z[64x32] = h[64x1024] @ Uslice[1024x32], bf16 2-term
// split (hiUhi + hiUlo + loUhi) on mma.sync.m16n8k16 -> ~fp16+ precision.
// Warps: mi = w&3 (16-row m-tile), ks = w>>2 (k-split of 256 = 4 ksteps/chunk? no:
//   chunk = k-slice of 64; warp's kstep within chunk = ks*16).
// U pre-packed in fragment order in smem (hi+lo, 128 KB) once per layer.
// h streamed per chunk (fp32 LDG -> hi/lo bf16 planes, padded stride 72 halves),
// double-buffered, 1 syncthreads per chunk. Epilogue reduces the 4 k-splits
// via smem (overlaying the dead chunk buffers), applies gates (c in regs).
// ---------------------------------------------------------------------------
#define OFF_UB     0
#define UB_PLANE   65536                 // hi plane 64 KB, lo plane 64 KB
#define OFF_A      131072                // 2 buffers x (hi 9216 + lo 9216)
#define A_PLANE    9216
#define A_BUF      18432
#define SMEM_BYTES (131072 + 36864)      // 167,936 B

__global__ __launch_bounds__(512) void lstm_layer_mma(const float* __restrict__ U,
                                                      int layer)
{
    extern __shared__ char smc[];
    const int tid  = threadIdx.x;
    const int lane = tid & 31;
    const int w    = tid >> 5;          // 0..15
    const int mi   = w & 3;             // m-tile (16 rows)
    const int ks   = w >> 2;            // k-split 0..3
    const int u0   = blockIdx.x * 8;

    // ---- pack U slice into fragment-order smem (hi & lo planes), once ----
    // slot s = (kstep(64) * 4 + nt) * 32 + lane ; 8 B per slot per plane:
    //   {b0 = bf16x2(k0,k0+1), b1 = bf16x2(k0+8,k0+9)} at n = nt*8 + lane>>2
    for (int s = tid; s < 8192; s += 512) {
        int ln  = s & 31;
        int nt  = (s >> 5) & 3;
        int kst = s >> 7;
        int gc  = (nt << 10) + u0 + (ln >> 2);
        int k0  = kst * 16 + (ln & 3) * 2;
        float v0 = U[(size_t)(k0    ) * G4 + gc];
        float v1 = U[(size_t)(k0 + 1) * G4 + gc];
        float v8 = U[(size_t)(k0 + 8) * G4 + gc];
        float v9 = U[(size_t)(k0 + 9) * G4 + gc];
        *(uint2*)(smc + OFF_UB + (size_t)s * 8) =
            make_uint2(pk_bf(v0, v1), pk_bf(v8, v9));
        *(uint2*)(smc + OFF_UB + UB_PLANE + (size_t)s * 8) =
            make_uint2(pk_bf(bf_res(v0), bf_res(v1)), pk_bf(bf_res(v8), bf_res(v9)));
    }

    // staging map: thread -> (row8 = tid>>3, kk = (tid&7)*8) : 8 floats per chunk
    const int row8 = tid >> 3;
    const int kk8  = (tid & 7) * 8;
    char* st_hi0 = smc + OFF_A + (size_t)row8 * 144 + (tid & 7) * 16;  // buf 0

    // A-fragment base offset (within a buffer): row = mi*16 + lane>>2,
    // k_local = ks*16 + (lane&3)*2 ; padded stride 72 halves -> conflict-free
    const int a_off = ((mi * 16 + (lane >> 2)) * 72 + ks * 16 + (lane & 3) * 2) * 2;

    float creg = 0.f;                   // cell state: thread owns (m=tid>>3, j=tid&7)
    const int em = tid >> 3, ej = tid & 7;

    float* ZR = (float*)(smc + OFF_A);  // epilogue overlay: [ks][64][34] fp32
    volatile unsigned* vb = g_bar8;

    __syncthreads();

    for (int t = 0; t < TT; t++) {
        const float* h_prev = g_hbuf[t & 1];
        float*       h_new  = g_hbuf[(t + 1) & 1];
        const float* hp = h_prev + (size_t)row8 * HH + kk8;

        float d[4][4];
#pragma unroll
        for (int nt = 0; nt < 4; nt++)
#pragma unroll
            for (int i = 0; i < 4; i++) d[nt][i] = 0.f;

        // stage chunk 0 into buf0
        {
            float4 q0 = __ldcg((const float4*)hp);
            float4 q1 = __ldcg((const float4*)(hp + 4));
            *(uint4*)st_hi0 = make_uint4(pk_bf(q0.x, q0.y), pk_bf(q0.z, q0.w),
                                         pk_bf(q1.x, q1.y), pk_bf(q1.z, q1.w));
            *(uint4*)(st_hi0 + A_PLANE) =
                make_uint4(pk_bf(bf_res(q0.x), bf_res(q0.y)), pk_bf(bf_res(q0.z), bf_res(q0.w)),
                           pk_bf(bf_res(q1.x), bf_res(q1.y)), pk_bf(bf_res(q1.z), bf_res(q1.w)));
        }
        // prefetch chunk 1
        float4 p0 = __ldcg((const float4*)(hp + 64));
        float4 p1 = __ldcg((const float4*)(hp + 68));
        __syncthreads();

        int buf = 0;
        for (int c = 0; c < 16; c++) {
            if (c < 15) {   // store prefetched chunk c+1 into buf^1
                char* sb = st_hi0 + (buf ^ 1) * A_BUF;
                *(uint4*)sb = make_uint4(pk_bf(p0.x, p0.y), pk_bf(p0.z, p0.w),
                                         pk_bf(p1.x, p1.y), pk_bf(p1.z, p1.w));
                *(uint4*)(sb + A_PLANE) =
                    make_uint4(pk_bf(bf_res(p0.x), bf_res(p0.y)), pk_bf(bf_res(p0.z), bf_res(p0.w)),
                               pk_bf(bf_res(p1.x), bf_res(p1.y)), pk_bf(bf_res(p1.z), bf_res(p1.w)));
            }
            if (c < 14) {   // prefetch chunk c+2
                p0 = __ldcg((const float4*)(hp + (c + 2) * 64));
                p1 = __ldcg((const float4*)(hp + (c + 2) * 64 + 4));
            }
            // mma on buf
            const char* ab = smc + OFF_A + buf * A_BUF + a_off;
            uint32_t ah0 = *(const uint32_t*)(ab);
            uint32_t ah1 = *(const uint32_t*)(ab + 1152);        // +8 rows (8*72*2)
            uint32_t ah2 = *(const uint32_t*)(ab + 16);          // +8 k halves
            uint32_t ah3 = *(const uint32_t*)(ab + 1168);
            uint32_t al0 = *(const uint32_t*)(ab + A_PLANE);
            uint32_t al1 = *(const uint32_t*)(ab + A_PLANE + 1152);
            uint32_t al2 = *(const uint32_t*)(ab + A_PLANE + 16);
            uint32_t al3 = *(const uint32_t*)(ab + A_PLANE + 1168);
#pragma unroll
            for (int nt = 0; nt < 4; nt++) {
                const char* bb = smc + OFF_UB +
                    (size_t)((((c * 4 + ks) * 4 + nt) * 32 + lane) * 8);
                uint2 bh = *(const uint2*)bb;
                uint2 bl = *(const uint2*)(bb + UB_PLANE);
                mma_bf16(d[nt], ah0, ah1, ah2, ah3, bh.x, bh.y);
                mma_bf16(d[nt], ah0, ah1, ah2, ah3, bl.x, bl.y);
                mma_bf16(d[nt], al0, al1, al2, al3, bh.x, bh.y);
            }
            __syncthreads();
            buf ^= 1;
        }

        // ---- epilogue: k-split reduction over smem (overlay chunk buffers) ----
        {
            int zw = ks * 2176 + (mi * 16 + (lane >> 2)) * 34 + (lane & 3) * 2;
#pragma unroll
            for (int nt = 0; nt < 4; nt++) {
                *(float2*)&ZR[zw + nt * 8]             = make_float2(d[nt][0], d[nt][1]);
                *(float2*)&ZR[zw + nt * 8 + 8 * 34]    = make_float2(d[nt][2], d[nt][3]);
            }
        }
        __syncthreads();
        {
            float z[4];
#pragma unroll
            for (int g = 0; g < 4; g++) {
                int zc = em * 34 + g * 8 + ej;
                z[g] = ZR[zc] + ZR[zc + 2176] + ZR[zc + 4352] + ZR[zc + 6528];
            }
            const float* xzp = g_xz + ((size_t)t * BB + em) * G4 + u0 + ej;
            float zi = z[0] + __ldg(xzp);
            float zf = z[1] + __ldg(xzp + 1024);
            float zg = z[2] + __ldg(xzp + 2048);
            float zo = z[3] + __ldg(xzp + 3072);
            float si = 1.f / (1.f + __expf(-zi));
            float sf = 1.f / (1.f + __expf(-zf));
            float so = 1.f / (1.f + __expf(-zo));
            float tg = tanhf(zg);
            float cn = sf * creg + si * tg;
            creg = cn;
            float hn = so * tanhf(cn);
            int idx = em * HH + u0 + ej;
            h_new[idx] = hn;
            if (layer == 0)
                g_seq1[(size_t)t * BB * HH + idx] = hn;
        }

        // ---- grid barrier (8 split counters) ----
        if (t < TT - 1) {
            __threadfence();
            __syncthreads();
            if (tid == 0) atomicAdd(&g_bar8[blockIdx.x & 7], 1u);
            unsigned target = (unsigned)(t + 1) * 16u;
            if (tid < 8) { while (vb[tid] < target) { } }
            __syncthreads();
        }
    }
}

// ---------------------------------------------------------------------------
// Final dense
// ---------------------------------------------------------------------------
__global__ void dense_out(const float* __restrict__ Wd, const float* __restrict__ bd,
                          float* __restrict__ out)
{
    int b = blockIdx.x;
    int o = threadIdx.x;
    const float* hp = g_hbuf[0] + (size_t)b * HH;   // T even -> final h in buf 0
    float acc = bd[o];
#pragma unroll 8
    for (int k = 0; k < HH; k++)
        acc += hp[k] * Wd[(size_t)k * OO + o];
    out[(size_t)b * OO + o] = acc;
}

// ---------------------------------------------------------------------------
// Launch sequence (recurrence at index 3 for the ncu capture)
// ---------------------------------------------------------------------------
extern "C" void kernel_launch(void* const* d_in, const int* in_sizes, int n_in,
                              void* d_out, int out_size)
{
    const float* x  = (const float*)d_in[0];
    const float* W1 = (const float*)d_in[1];
    const float* U1 = (const float*)d_in[2];
    const float* b1 = (const float*)d_in[3];
    const float* W2 = (const float*)d_in[4];
    const float* U2 = (const float*)d_in[5];
    const float* b2 = (const float*)d_in[6];
    const float* Wd = (const float*)d_in[7];
    const float* bd = (const float*)d_in[8];
    float* out = (float*)d_out;

    cudaFuncSetAttribute(lstm_layer_mma,
                         cudaFuncAttributeMaxDynamicSharedMemorySize, SMEM_BYTES);

    dim3 gemm_grid(G4 / 128, MTOT / 128);

    // ---- Layer 1 ----
    gemm_big<0><<<gemm_grid, 256>>>(x, W1, b1, DD);          // 0
    zero_hc<<<(BB * HH + 255) / 256, 256>>>();               // 1
    zero_hc<<<(BB * HH + 255) / 256, 256>>>();               // 2 (spacer)
    lstm_layer_mma<<<128, 512, SMEM_BYTES>>>(U1, 0);         // 3 <- profiled

    // ---- Layer 2 ----
    gemm_big<1><<<gemm_grid, 256>>>(nullptr, W2, b2, HH);    // 4
    zero_hc<<<(BB * HH + 255) / 256, 256>>>();               // 5
    lstm_layer_mma<<<128, 512, SMEM_BYTES>>>(U2, 1);         // 6

    // ---- Dense head ----
    dense_out<<<BB, OO>>>(Wd, bd, out);                      // 7
}

// round 11
// speedup vs baseline: 2.5408x; 1.3366x over previous
#include <cuda_runtime.h>
#include <cuda_bf16.h>
#include <math.h>
#include <stdint.h>

// Problem constants
#define BB 64
#define TT 256
#define DD 512
#define HH 1024         // H1 == H2
#define G4 4096         // 4*H
#define OO 512
#define MTOT (BB*TT)    // 16384

typedef unsigned long long ull;

// ---------------------------------------------------------------------------
// f32x2 packed-FMA helpers (sm_103a FFMA2) — used by the xz GEMM
// ---------------------------------------------------------------------------
__device__ __forceinline__ void ffma2(ull& d, ull a, ull b) {
    asm("fma.rn.f32x2 %0, %1, %2, %0;" : "+l"(d) : "l"(a), "l"(b));
}
__device__ __forceinline__ ull pack_dup(float x) {
    ull r; asm("mov.b64 %0, {%1, %1};" : "=l"(r) : "f"(x)); return r;
}
__device__ __forceinline__ ull pack2(float lo, float hi) {
    ull r; asm("mov.b64 %0, {%1, %2};" : "=l"(r) : "f"(lo), "f"(hi)); return r;
}
__device__ __forceinline__ float lo_f(ull v) { return __uint_as_float((unsigned)(v & 0xFFFFFFFFull)); }
__device__ __forceinline__ float hi_f(ull v) { return __uint_as_float((unsigned)(v >> 32)); }

// ---------------------------------------------------------------------------
// bf16 split helpers
// ---------------------------------------------------------------------------
__device__ __forceinline__ unsigned pk_bf(float a, float b) {
    unsigned short ua = __bfloat16_as_ushort(__float2bfloat16_rn(a));
    unsigned short ub = __bfloat16_as_ushort(__float2bfloat16_rn(b));
    return (unsigned)ua | ((unsigned)ub << 16);
}
__device__ __forceinline__ float bf_res(float x) {
    return x - __bfloat162float(__float2bfloat16_rn(x));
}

// mma.sync m16n8k16 bf16 (baseline PTX, sm_80+, valid on compute_103)
__device__ __forceinline__ void mma_bf16(float* d,
                                         uint32_t a0, uint32_t a1, uint32_t a2, uint32_t a3,
                                         uint32_t b0, uint32_t b1) {
    asm volatile(
        "mma.sync.aligned.m16n8k16.row.col.f32.bf16.bf16.f32 "
        "{%0,%1,%2,%3}, {%4,%5,%6,%7}, {%8,%9}, {%0,%1,%2,%3};"
        : "+f"(d[0]), "+f"(d[1]), "+f"(d[2]), "+f"(d[3])
        : "r"(a0), "r"(a1), "r"(a2), "r"(a3), "r"(b0), "r"(b1));
}

// cp.async (sm_80 PTX) helpers
__device__ __forceinline__ void cp16(uint32_t dst, const void* src) {
    asm volatile("cp.async.cg.shared.global [%0], [%1], 16;"
                 :: "r"(dst), "l"(src) : "memory");
}
#define CP_COMMIT() asm volatile("cp.async.commit_group;" ::: "memory")
#define CP_WAIT2()  asm volatile("cp.async.wait_group 2;" ::: "memory")
#define CP_WAIT0()  asm volatile("cp.async.wait_group 0;" ::: "memory")

__device__ __forceinline__ uint32_t smem_u32(const void* p) {
    uint32_t a;
    asm("{ .reg .u64 t; cvta.to.shared.u64 t, %1; cvt.u32.u64 %0, t; }" : "=r"(a) : "l"(p));
    return a;
}

// ---------------------------------------------------------------------------
// Static device scratch
// ---------------------------------------------------------------------------
__device__ float g_xz[(size_t)MTOT * G4];     // 256 MB  z-pre (natural layout)
__device__ float g_seq1[(size_t)MTOT * HH];   // 64 MB   layer-1 h sequence
__device__ __nv_bfloat16 g_hhi[2][BB * HH];   // h hi plane, ping-pong
__device__ __nv_bfloat16 g_hlo[2][BB * HH];   // h lo (residual) plane
__device__ unsigned g_bar8[8];                // split grid-barrier counters

__global__ void zero_hc()
{
    int idx = blockIdx.x * blockDim.x + threadIdx.x;
    if (idx < BB * HH) {
        g_hhi[0][idx] = __float2bfloat16(0.f);
        g_hlo[0][idx] = __float2bfloat16(0.f);
    }
    if (idx < 8) g_bar8[idx] = 0u;
}

// ---------------------------------------------------------------------------
// Big GEMM (fp32 FFMA2, known good): g_xz[m][n] = sum_k A[m][k]*W[k][n] + b[n]
// ---------------------------------------------------------------------------
template<int MODE>
__global__ __launch_bounds__(256) void gemm_big(const float* __restrict__ Ain,
                                                const float* __restrict__ W,
                                                const float* __restrict__ bias,
                                                int K)
{
    __shared__ float As[2][16][136];
    __shared__ float Bs[2][16][136];

    const int tid  = threadIdx.x;
    const int tx   = tid & 15;
    const int ty   = tid >> 4;
    const int row0 = blockIdx.y * 128;
    const int n0   = blockIdx.x * 128;

    const float* A = (MODE == 0) ? Ain : (const float*)g_seq1;

    const int am0 = tid >> 2, aq0 = (tid & 3) * 4;
    const int am1 = (tid + 256) >> 2, aq1 = (tid & 3) * 4;
    const float *ap0, *ap1;
    {
        int mg0 = row0 + am0, mg1 = row0 + am1;
        if (MODE == 0) {
            ap0 = A + ((size_t)((mg0 & 63) * TT + (mg0 >> 6))) * DD;
            ap1 = A + ((size_t)((mg1 & 63) * TT + (mg1 >> 6))) * DD;
        } else {
            ap0 = A + (size_t)mg0 * K;
            ap1 = A + (size_t)mg1 * K;
        }
    }
    const int bk0 = tid >> 5, bq0 = (tid & 31) * 4;
    const int bk1 = (tid + 256) >> 5, bq1 = (tid & 31) * 4;

    ull acc[8][4];
    {
        float b0 = bias[n0 + tx * 4 + 0], b1 = bias[n0 + tx * 4 + 1];
        float b2 = bias[n0 + tx * 4 + 2], b3 = bias[n0 + tx * 4 + 3];
        float b4 = bias[n0 + 64 + tx * 4 + 0], b5 = bias[n0 + 64 + tx * 4 + 1];
        float b6 = bias[n0 + 64 + tx * 4 + 2], b7 = bias[n0 + 64 + tx * 4 + 3];
        ull p0 = pack2(b0, b1), p1 = pack2(b2, b3), p2 = pack2(b4, b5), p3 = pack2(b6, b7);
#pragma unroll
        for (int r = 0; r < 8; r++) { acc[r][0] = p0; acc[r][1] = p1; acc[r][2] = p2; acc[r][3] = p3; }
    }

    float4 pa0 = *(const float4*)(ap0 + aq0);
    float4 pa1 = *(const float4*)(ap1 + aq1);
    float4 pb0 = *(const float4*)(W + (size_t)bk0 * G4 + n0 + bq0);
    float4 pb1 = *(const float4*)(W + (size_t)bk1 * G4 + n0 + bq1);
    As[0][aq0 + 0][am0] = pa0.x; As[0][aq0 + 1][am0] = pa0.y;
    As[0][aq0 + 2][am0] = pa0.z; As[0][aq0 + 3][am0] = pa0.w;
    As[0][aq1 + 0][am1] = pa1.x; As[0][aq1 + 1][am1] = pa1.y;
    As[0][aq1 + 2][am1] = pa1.z; As[0][aq1 + 3][am1] = pa1.w;
    *(float4*)&Bs[0][bk0][bq0] = pb0;
    *(float4*)&Bs[0][bk1][bq1] = pb1;
    __syncthreads();

    int buf = 0;
    for (int k0 = 0; k0 < K; k0 += 16) {
        const bool more = (k0 + 16) < K;
        if (more) {
            pa0 = *(const float4*)(ap0 + k0 + 16 + aq0);
            pa1 = *(const float4*)(ap1 + k0 + 16 + aq1);
            pb0 = *(const float4*)(W + (size_t)(k0 + 16 + bk0) * G4 + n0 + bq0);
            pb1 = *(const float4*)(W + (size_t)(k0 + 16 + bk1) * G4 + n0 + bq1);
        }
#pragma unroll
        for (int k = 0; k < 16; k++) {
            ulonglong2 blo = *(const ulonglong2*)&Bs[buf][k][tx * 4];
            ulonglong2 bhi = *(const ulonglong2*)&Bs[buf][k][64 + tx * 4];
            float a[8];
            *(float4*)&a[0] = *(const float4*)&As[buf][k][ty * 4];
            *(float4*)&a[4] = *(const float4*)&As[buf][k][64 + ty * 4];
#pragma unroll
            for (int r = 0; r < 8; r++) {
                ull ap = pack_dup(a[r]);
                ffma2(acc[r][0], ap, blo.x);
                ffma2(acc[r][1], ap, blo.y);
                ffma2(acc[r][2], ap, bhi.x);
                ffma2(acc[r][3], ap, bhi.y);
            }
        }
        if (more) {
            int nb = buf ^ 1;
            As[nb][aq0 + 0][am0] = pa0.x; As[nb][aq0 + 1][am0] = pa0.y;
            As[nb][aq0 + 2][am0] = pa0.z; As[nb][aq0 + 3][am0] = pa0.w;
            As[nb][aq1 + 0][am1] = pa1.x; As[nb][aq1 + 1][am1] = pa1.y;
            As[nb][aq1 + 2][am1] = pa1.z; As[nb][aq1 + 3][am1] = pa1.w;
            *(float4*)&Bs[nb][bk0][bq0] = pb0;
            *(float4*)&Bs[nb][bk1][bq1] = pb1;
        }
        __syncthreads();
        buf ^= 1;
    }

#pragma unroll
    for (int r = 0; r < 8; r++) {
        int m = row0 + ((r < 4) ? (ty * 4 + r) : (64 + ty * 4 + (r - 4)));
        float* op = g_xz + (size_t)m * G4 + n0;
        float4 v0 = make_float4(lo_f(acc[r][0]), hi_f(acc[r][0]),
                                lo_f(acc[r][1]), hi_f(acc[r][1]));
        float4 v1 = make_float4(lo_f(acc[r][2]), hi_f(acc[r][2]),
                                lo_f(acc[r][3]), hi_f(acc[r][3]));
        *(float4*)(op + tx * 4)      = v0;
        *(float4*)(op + 64 + tx * 4) = v1;
    }
}

// ---------------------------------------------------------------------------
// Persistent mma.sync recurrence v2. 128 CTAs x 512 thr (16 warps), 1 CTA/SM.
// h is kept in GLOBAL bf16 hi/lo planes written by the epilogue (producer-side
// conversion, done once chip-wide instead of 128x). Staging = cp.async.cg
// global->smem, 4-stage pipeline (3 chunks of k=64 in flight).
// Z[64x32] = h[64x1024] @ Uslice; 2-term bf16 split (hiUhi + hiUlo + loUhi).
// U fragments pre-packed in smem, hi/lo interleaved per 16B slot (1 LDS.128).
// c state in registers; 8-counter grid barrier between steps.
// ---------------------------------------------------------------------------
#define OFF_UB     0
#define OFF_A      131072                // 4 bufs x (hi 9216 + lo 9216)
#define A_PLANE    9216
#define A_BUF      18432
#define SMEM_BYTES (131072 + 4 * 18432)  // 204,800 B

__global__ __launch_bounds__(512) void lstm_layer_mma(const float* __restrict__ U,
                                                      int layer)
{
    extern __shared__ char smc[];
    const int tid  = threadIdx.x;
    const int lane = tid & 31;
    const int w    = tid >> 5;          // 0..15
    const int mi   = w & 3;             // m-tile (16 rows)
    const int ks   = w >> 2;            // k-split 0..3
    const int u0   = blockIdx.x * 8;

    // ---- pack U slice into fragment-order smem, hi/lo interleaved 16B ----
    // slot s = (kstep(64)*4 + nt)*32 + lane : {bh.x,bh.y,bl.x,bl.y}
    for (int s = tid; s < 8192; s += 512) {
        int ln  = s & 31;
        int nt  = (s >> 5) & 3;
        int kst = s >> 7;
        int gc  = (nt << 10) + u0 + (ln >> 2);
        int k0  = kst * 16 + (ln & 3) * 2;
        float v0 = U[(size_t)(k0    ) * G4 + gc];
        float v1 = U[(size_t)(k0 + 1) * G4 + gc];
        float v8 = U[(size_t)(k0 + 8) * G4 + gc];
        float v9 = U[(size_t)(k0 + 9) * G4 + gc];
        *(uint4*)(smc + OFF_UB + (size_t)s * 16) =
            make_uint4(pk_bf(v0, v1), pk_bf(v8, v9),
                       pk_bf(bf_res(v0), bf_res(v1)), pk_bf(bf_res(v8), bf_res(v9)));
    }

    // staging map: thread -> (row8 = tid>>3, 16B segment tid&7) per plane
    const int row8 = tid >> 3;
    const int kseg = tid & 7;
    const uint32_t smbase = smem_u32(smc);
    const uint32_t st_hi  = smbase + OFF_A + (uint32_t)row8 * 144 + kseg * 16;
    const int      goff   = row8 * HH + kseg * 8;   // element offset into planes

    // A-fragment base offset within a buffer (padded stride 72 halves)
    const int a_off = ((mi * 16 + (lane >> 2)) * 72 + ks * 16 + (lane & 3) * 2) * 2;

    float creg = 0.f;                   // cell state: thread owns (em, ej)
    const int em = tid >> 3, ej = tid & 7;

    float* ZR = (float*)(smc + OFF_A);  // epilogue overlay: [ks][64][34] fp32
    volatile unsigned* vb = g_bar8;

    __syncthreads();

    for (int t = 0; t < TT; t++) {
        const __nv_bfloat16* phi = g_hhi[t & 1] + goff;
        const __nv_bfloat16* plo = g_hlo[t & 1] + goff;

        // prefetch xz (used only in epilogue)
        const float* xzp = g_xz + ((size_t)t * BB + em) * G4 + u0 + ej;
        float x0 = __ldg(xzp);
        float x1 = __ldg(xzp + 1024);
        float x2 = __ldg(xzp + 2048);
        float x3 = __ldg(xzp + 3072);

        // pipeline prologue: issue chunks 0..2
#pragma unroll
        for (int pc = 0; pc < 3; pc++) {
            cp16(st_hi + pc * A_BUF,           phi + pc * 64);
            cp16(st_hi + pc * A_BUF + A_PLANE, plo + pc * 64);
            CP_COMMIT();
        }

        float d[4][4];
#pragma unroll
        for (int nt = 0; nt < 4; nt++)
#pragma unroll
            for (int i = 0; i < 4; i++) d[nt][i] = 0.f;

        for (int c = 0; c < 16; c++) {
            CP_WAIT2();
            __syncthreads();

            const char* ab = smc + OFF_A + (c & 3) * A_BUF + a_off;
            uint32_t ah0 = *(const uint32_t*)(ab);
            uint32_t ah1 = *(const uint32_t*)(ab + 1152);
            uint32_t ah2 = *(const uint32_t*)(ab + 16);
            uint32_t ah3 = *(const uint32_t*)(ab + 1168);
            uint32_t al0 = *(const uint32_t*)(ab + A_PLANE);
            uint32_t al1 = *(const uint32_t*)(ab + A_PLANE + 1152);
            uint32_t al2 = *(const uint32_t*)(ab + A_PLANE + 16);
            uint32_t al3 = *(const uint32_t*)(ab + A_PLANE + 1168);
#pragma unroll
            for (int nt = 0; nt < 4; nt++) {
                uint4 bv = *(const uint4*)(smc + OFF_UB +
                    (size_t)((((c * 4 + ks) * 4 + nt) * 32 + lane) * 16));
                mma_bf16(d[nt], ah0, ah1, ah2, ah3, bv.x, bv.y);
                mma_bf16(d[nt], ah0, ah1, ah2, ah3, bv.z, bv.w);
                mma_bf16(d[nt], al0, al1, al2, al3, bv.x, bv.y);
            }

            if (c < 13) {   // issue chunk c+3 into buf (c+3)&3
                cp16(st_hi + ((c + 3) & 3) * A_BUF,           phi + (c + 3) * 64);
                cp16(st_hi + ((c + 3) & 3) * A_BUF + A_PLANE, plo + (c + 3) * 64);
            }
            CP_COMMIT();    // empty group when c >= 13 keeps wait-count uniform
        }
        CP_WAIT0();
        __syncthreads();    // all mmas done before ZR overlays the A buffers

        // ---- k-split reduction over smem overlay ----
        {
            int zw = ks * 2176 + (mi * 16 + (lane >> 2)) * 34 + (lane & 3) * 2;
#pragma unroll
            for (int nt = 0; nt < 4; nt++) {
                *(float2*)&ZR[zw + nt * 8]          = make_float2(d[nt][0], d[nt][1]);
                *(float2*)&ZR[zw + nt * 8 + 8 * 34] = make_float2(d[nt][2], d[nt][3]);
            }
        }
        __syncthreads();
        {
            float z[4];
#pragma unroll
            for (int g = 0; g < 4; g++) {
                int zc = em * 34 + g * 8 + ej;
                z[g] = ZR[zc] + ZR[zc + 2176] + ZR[zc + 4352] + ZR[zc + 6528];
            }
            float zi = z[0] + x0;
            float zf = z[1] + x1;
            float zg = z[2] + x2;
            float zo = z[3] + x3;
            float si = 1.f / (1.f + __expf(-zi));
            float sf = 1.f / (1.f + __expf(-zf));
            float so = 1.f / (1.f + __expf(-zo));
            float tg = tanhf(zg);
            float cn = sf * creg + si * tg;
            creg = cn;
            float hn = so * tanhf(cn);
            // producer-side hi/lo split into the next ping-pong planes
            __nv_bfloat16 hb = __float2bfloat16_rn(hn);
            __nv_bfloat16 lb = __float2bfloat16_rn(hn - __bfloat162float(hb));
            int idx = em * HH + u0 + ej;
            g_hhi[(t + 1) & 1][idx] = hb;
            g_hlo[(t + 1) & 1][idx] = lb;
            if (layer == 0)
                g_seq1[(size_t)t * BB * HH + idx] = hn;
        }

        // ---- grid barrier (8 split counters) ----
        if (t < TT - 1) {
            __threadfence();
            __syncthreads();
            if (tid == 0) atomicAdd(&g_bar8[blockIdx.x & 7], 1u);
            unsigned target = (unsigned)(t + 1) * 16u;
            if (tid < 8) { while (vb[tid] < target) { } }
            __syncthreads();
        }
    }
}

// ---------------------------------------------------------------------------
// Final dense: h_last reconstructed from hi+lo planes (buf 0, T even)
// ---------------------------------------------------------------------------
__global__ void dense_out(const float* __restrict__ Wd, const float* __restrict__ bd,
                          float* __restrict__ out)
{
    int b = blockIdx.x;
    int o = threadIdx.x;
    const __nv_bfloat16* hi = g_hhi[0] + (size_t)b * HH;
    const __nv_bfloat16* lo = g_hlo[0] + (size_t)b * HH;
    float acc = bd[o];
#pragma unroll 8
    for (int k = 0; k < HH; k++) {
        float h = __bfloat162float(hi[k]) + __bfloat162float(lo[k]);
        acc += h * Wd[(size_t)k * OO + o];
    }
    out[(size_t)b * OO + o] = acc;
}

// ---------------------------------------------------------------------------
// Launch sequence (recurrence at index 3 for the ncu capture)
// ---------------------------------------------------------------------------
extern "C" void kernel_launch(void* const* d_in, const int* in_sizes, int n_in,
                              void* d_out, int out_size)
{
    const float* x  = (const float*)d_in[0];
    const float* W1 = (const float*)d_in[1];
    const float* U1 = (const float*)d_in[2];
    const float* b1 = (const float*)d_in[3];
    const float* W2 = (const float*)d_in[4];
    const float* U2 = (const float*)d_in[5];
    const float* b2 = (const float*)d_in[6];
    const float* Wd = (const float*)d_in[7];
    const float* bd = (const float*)d_in[8];
    float* out = (float*)d_out;

    cudaFuncSetAttribute(lstm_layer_mma,
                         cudaFuncAttributeMaxDynamicSharedMemorySize, SMEM_BYTES);

    dim3 gemm_grid(G4 / 128, MTOT / 128);

    // ---- Layer 1 ----
    gemm_big<0><<<gemm_grid, 256>>>(x, W1, b1, DD);          // 0
    zero_hc<<<(BB * HH + 255) / 256, 256>>>();               // 1
    zero_hc<<<(BB * HH + 255) / 256, 256>>>();               // 2 (spacer)
    lstm_layer_mma<<<128, 512, SMEM_BYTES>>>(U1, 0);         // 3 <- profiled

    // ---- Layer 2 ----
    gemm_big<1><<<gemm_grid, 256>>>(nullptr, W2, b2, HH);    // 4
    zero_hc<<<(BB * HH + 255) / 256, 256>>>();               // 5
    lstm_layer_mma<<<128, 512, SMEM_BYTES>>>(U2, 1);         // 6

    // ---- Dense head ----
    dense_out<<<BB, OO>>>(Wd, bd, out);                      // 7
}